// round 2
// baseline (speedup 1.0000x reference)
#include <cuda_runtime.h>

// ---------------------------------------------------------------------------
// SWIN attention layer, fused per-window implementation (fp32 baseline).
// M=32, H=W=64, D=256, 8x8 windows, 8 heads (hd=32), shift 4.
// Pass 1: unshifted windows, no mask  -> g_y (device scratch)
// Pass 2: shifted windows (+swin mask) on g_y -> d_out (with inverse roll)
// One CTA per window (2048 CTAs/pass), 256 threads.
// ---------------------------------------------------------------------------

namespace {
constexpr int Mb  = 32;
constexpr int Hh  = 64;
constexpr int Wg  = 64;
constexpr int Dd  = 256;
constexpr int NHh = 8;
constexpr int HDd = 32;     // head dim
constexpr int WSs = 64;     // tokens per window (8x8)
constexpr int NWIN = Mb * 64;   // 2048 windows total
constexpr float SCALE = 0.17677669529663687f;   // 1/sqrt(32)
constexpr float NEGM  = -1e9f;
}

// 128 MB intermediate between pass 1 and pass 2 (static device scratch; no alloc).
__device__ float g_y[Mb * Hh * Wg * Dd];

struct SmemT {
    float xs[WSs][Dd];          // input window     64x256  (64 KB)
    float outs[WSs][Dd];        // concat head outs 64x256  (64 KB)
    float q[WSs][HDd];          // 64x32
    float v[WSs][HDd];          // 64x32
    float kT[HDd][WSs + 1];     // transposed K, padded (32x65)
    float sc[WSs][WSs + 1];     // scores, padded (64x65)
    int   regid[WSs];           // swin mask region id per token
};

template <bool SHIFTED>
__global__ __launch_bounds__(256, 1)
void swin_win_kernel(const float* __restrict__ xin,
                     const float* __restrict__ wqkv,
                     const float* __restrict__ bqkv,
                     const float* __restrict__ wo,
                     const float* __restrict__ bo,
                     float* __restrict__ outp)
{
    extern __shared__ char smraw[];
    SmemT& sm = *reinterpret_cast<SmemT*>(smraw);

    const int t    = threadIdx.x;
    const int lane = t & 31;
    const int wrp  = t >> 5;      // warp id 0..7

    const int win = blockIdx.x;   // 0..2047
    const int b   = win >> 6;
    const int w   = win & 63;
    const int wi  = w >> 3;
    const int wj  = w & 7;

    const float* src = SHIFTED ? (const float*)g_y : xin;
    float*       dst = SHIFTED ? outp : (float*)g_y;

    // --- region ids for the swin shift mask (from UNSHIFTED img coords) ---
    if (t < WSs) {
        const int ti = t >> 3, tj = t & 7;
        const int gr = wi * 8 + ti;
        const int gc = wj * 8 + tj;
        const int rr = (gr < 56) ? 0 : (gr < 60 ? 1 : 2);
        const int cc = (gc < 56) ? 0 : (gc < 60 ? 1 : 2);
        sm.regid[t] = rr * 3 + cc;
    }

    // --- load the window: 64 tokens x 256 dims, float4 vectorized ---
    for (int idx = t; idx < WSs * 64; idx += 256) {
        const int s  = idx >> 6;        // token
        const int d4 = idx & 63;        // float4 index within 256 dims
        const int ti = s >> 3, tj = s & 7;
        int gr = wi * 8 + ti;
        int gc = wj * 8 + tj;
        if (SHIFTED) { gr = (gr + 4) & 63; gc = (gc + 4) & 63; }
        const float4* p =
            reinterpret_cast<const float4*>(src + ((size_t)((b * Hh + gr) * Wg + gc)) * Dd) + d4;
        reinterpret_cast<float4*>(&sm.xs[s][0])[d4] = *p;
    }
    __syncthreads();

    // =========================== per-head loop ===========================
    for (int h = 0; h < NHh; ++h) {
        // --- A: q/k/v = x @ Wqkv slices (+bias). thread: col=lane, rows wrp+8r
        {
            const int colq = h * HDd + lane;
            float accq[8], acck[8], accv[8];
            const float bq = bqkv[colq];
            const float bk = bqkv[256 + colq];
            const float bv = bqkv[512 + colq];
#pragma unroll
            for (int r = 0; r < 8; r++) { accq[r] = bq; acck[r] = bk; accv[r] = bv; }

            const float* wp = wqkv + colq;
#pragma unroll 4
            for (int kk = 0; kk < Dd; kk++) {
                const float a  = wp[kk * 768];
                const float bb = wp[kk * 768 + 256];
                const float c  = wp[kk * 768 + 512];
#pragma unroll
                for (int r = 0; r < 8; r++) {
                    const float xv = sm.xs[wrp + 8 * r][kk];   // warp broadcast
                    accq[r] = fmaf(xv, a,  accq[r]);
                    acck[r] = fmaf(xv, bb, acck[r]);
                    accv[r] = fmaf(xv, c,  accv[r]);
                }
            }
#pragma unroll
            for (int r = 0; r < 8; r++) {
                const int row = wrp + 8 * r;
                sm.q[row][lane]  = accq[r];
                sm.kT[lane][row] = acck[r];   // padded, conflict-free
                sm.v[row][lane]  = accv[r];
            }
        }
        __syncthreads();

        // --- B: scores = q @ kT * scale (+mask) ---
        {
#pragma unroll
            for (int ii = 0; ii < 8; ii++) {
                const int i = wrp + 8 * ii;
                float s0 = 0.f, s1 = 0.f;
#pragma unroll
                for (int d = 0; d < HDd; d++) {
                    const float qv = sm.q[i][d];               // warp broadcast
                    s0 = fmaf(qv, sm.kT[d][lane],      s0);
                    s1 = fmaf(qv, sm.kT[d][lane + 32], s1);
                }
                s0 *= SCALE; s1 *= SCALE;
                if (SHIFTED) {
                    const int ri = sm.regid[i];
                    if (ri != sm.regid[lane])      s0 += NEGM;
                    if (ri != sm.regid[lane + 32]) s1 += NEGM;
                }
                sm.sc[i][lane]      = s0;
                sm.sc[i][lane + 32] = s1;
            }
        }
        __syncthreads();

        // --- C: row softmax (4 threads per row, 16 elems each) ---
        {
            const int row = t >> 2;
            const int sub = t & 3;
            float* sr = &sm.sc[row][sub * 16];
            float mx = sr[0];
#pragma unroll
            for (int k = 1; k < 16; k++) mx = fmaxf(mx, sr[k]);
            mx = fmaxf(mx, __shfl_xor_sync(0xffffffffu, mx, 1));
            mx = fmaxf(mx, __shfl_xor_sync(0xffffffffu, mx, 2));
            float sum = 0.f;
#pragma unroll
            for (int k = 0; k < 16; k++) {
                const float e = __expf(sr[k] - mx);
                sr[k] = e;
                sum += e;
            }
            sum += __shfl_xor_sync(0xffffffffu, sum, 1);
            sum += __shfl_xor_sync(0xffffffffu, sum, 2);
            const float inv = 1.0f / sum;
#pragma unroll
            for (int k = 0; k < 16; k++) sr[k] *= inv;
        }
        __syncthreads();

        // --- D: out_h = P @ v -> outs[:, h*32 + lane] ---
        {
            float acc[8];
#pragma unroll
            for (int ii = 0; ii < 8; ii++) acc[ii] = 0.f;
            for (int j = 0; j < WSs; j++) {
                const float vv = sm.v[j][lane];
#pragma unroll
                for (int ii = 0; ii < 8; ii++)
                    acc[ii] = fmaf(sm.sc[wrp + 8 * ii][j], vv, acc[ii]);
            }
#pragma unroll
            for (int ii = 0; ii < 8; ii++)
                sm.outs[wrp + 8 * ii][h * HDd + lane] = acc[ii];
        }
        __syncthreads();   // protect q/kT/v/sc before next head rewrites them
    }

    // --- E: output projection y = outs @ Wo + bo, 8x8 register tile/thread ---
    {
        float acc[8][8];
#pragma unroll
        for (int ii = 0; ii < 8; ii++)
#pragma unroll
            for (int c = 0; c < 8; c++) acc[ii][c] = bo[lane + 32 * c];

        for (int din = 0; din < Dd; din++) {
            float wr[8];
            const float* wrow = wo + (size_t)din * Dd + lane;
#pragma unroll
            for (int c = 0; c < 8; c++) wr[c] = wrow[32 * c];
#pragma unroll
            for (int ii = 0; ii < 8; ii++) {
                const float a = sm.outs[wrp + 8 * ii][din];    // warp broadcast
#pragma unroll
                for (int c = 0; c < 8; c++) acc[ii][c] = fmaf(a, wr[c], acc[ii][c]);
            }
        }

#pragma unroll
        for (int ii = 0; ii < 8; ii++) {
            const int s  = wrp + 8 * ii;
            const int ti = s >> 3, tj = s & 7;
            int gr = wi * 8 + ti;
            int gc = wj * 8 + tj;
            if (SHIFTED) { gr = (gr + 4) & 63; gc = (gc + 4) & 63; }  // inverse roll
            float* d = dst + ((size_t)((b * Hh + gr) * Wg + gc)) * Dd + lane;
#pragma unroll
            for (int c = 0; c < 8; c++) d[32 * c] = acc[ii][c];
        }
    }
}

extern "C" void kernel_launch(void* const* d_in, const int* in_sizes, int n_in,
                              void* d_out, int out_size)
{
    const float* x    = (const float*)d_in[0];
    const float* wqkv = (const float*)d_in[1];
    const float* bqkv = (const float*)d_in[2];
    const float* wo   = (const float*)d_in[3];
    const float* bo   = (const float*)d_in[4];
    float* out = (float*)d_out;

    const int smem = (int)sizeof(SmemT);
    cudaFuncSetAttribute(swin_win_kernel<false>,
                         cudaFuncAttributeMaxDynamicSharedMemorySize, smem);
    cudaFuncSetAttribute(swin_win_kernel<true>,
                         cudaFuncAttributeMaxDynamicSharedMemorySize, smem);

    // pass 1: unshifted, writes g_y
    swin_win_kernel<false><<<NWIN, 256, smem>>>(x, wqkv, bqkv, wo, bo, nullptr);
    // pass 2: shifted + mask, reads g_y, writes d_out with inverse roll
    swin_win_kernel<true><<<NWIN, 256, smem>>>(x, wqkv, bqkv, wo, bo, out);
}

// round 5
// speedup vs baseline: 3.0262x; 3.0262x over previous
#include <cuda_runtime.h>
#include <cstdint>

// ===========================================================================
// SWIN attention layer on GB300 (sm_103 base target — NO tcgen05).
// GEMMs use mma.sync.m16n8k8 tf32 + ldmatrix (sm_80+ PTX, tensor pipe).
// Pipeline per pass: QKV GEMM -> per-window attention (fp32) -> proj GEMM.
// Pass 1 unshifted -> g_y; pass 2 shifted (+swin mask) -> d_out.
// ===========================================================================

namespace {
constexpr int TOK = 32 * 64 * 64;          // 131072 tokens
constexpr int MT  = TOK / 128;             // 1024 M-tiles
constexpr float SCALE = 0.17677669529663687f;
constexpr float NEGM  = -1e9f;
constexpr int AST = 36;                    // A/B smem row stride in floats
constexpr int CHUNK_B = 128 * AST * 4;     // 18432 bytes per [128][36] tile
constexpr int GSMEM = 8 * CHUNK_B + 2 * CHUNK_B;   // A(8 chunks) + B(2 bufs)
}

// static device scratch
__device__ float    g_qkv[(size_t)TOK * 768];
__device__ float    g_ao [(size_t)TOK * 256];
__device__ float    g_y  [(size_t)TOK * 256];
__device__ uint32_t g_wqkv_p[6 * 8 * 128 * AST];   // packed tf32 W_qkv
__device__ uint32_t g_wo_p  [2 * 8 * 128 * AST];   // packed tf32 W_o

__device__ __forceinline__ uint32_t smem_u32(const void* p) {
    uint32_t a;
    asm("{ .reg .u64 t; cvta.to.shared.u64 t, %1; cvt.u32.u64 %0, t; }"
        : "=r"(a) : "l"(p));
    return a;
}
__device__ __forceinline__ uint32_t f2tf32(float f) {
    uint32_t u;
    asm("cvt.rna.tf32.f32 %0, %1;" : "=r"(u) : "f"(f));
    return u;
}
__device__ __forceinline__ void ldsm_x4(uint32_t* r, uint32_t a) {
    asm volatile("ldmatrix.sync.aligned.m8n8.x4.shared.b16 {%0,%1,%2,%3}, [%4];"
                 : "=r"(r[0]), "=r"(r[1]), "=r"(r[2]), "=r"(r[3]) : "r"(a));
}
__device__ __forceinline__ void mma_tf32(float* c, const uint32_t* a,
                                         uint32_t b0, uint32_t b1) {
    asm volatile(
        "mma.sync.aligned.m16n8k8.row.col.f32.tf32.tf32.f32 "
        "{%0,%1,%2,%3}, {%4,%5,%6,%7}, {%8,%9}, {%0,%1,%2,%3};"
        : "+f"(c[0]), "+f"(c[1]), "+f"(c[2]), "+f"(c[3])
        : "r"(a[0]), "r"(a[1]), "r"(a[2]), "r"(a[3]), "r"(b0), "r"(b1));
}

// token -> image element offset, optional +4 roll on both spatial axes
template <bool SHIFT>
__device__ __forceinline__ size_t tok_img_off(int T) {
    const int win = T >> 6, pos = T & 63;
    const int b = win >> 6, w = win & 63;
    int gr = (w >> 3) * 8 + (pos >> 3);
    int gc = (w & 7) * 8 + (pos & 7);
    if (SHIFT) { gr = (gr + 4) & 63; gc = (gc + 4) & 63; }
    return ((size_t)((b * 64 + gr) * 64 + gc)) * 256;
}

// ---------------------------------------------------------------------------
// weight pre-pack: W[K=256][N] fp32 -> per (nt, kc) blocks [n=128][k=32] tf32,
// n-major rows of stride AST=36 (ldmatrix-ready smem image).
// ---------------------------------------------------------------------------
__global__ void prepack_w(const float* __restrict__ w, uint32_t* __restrict__ dst,
                          int NT)
{
    const int LDB = NT * 128;
    const int total = NT * 8 * 128 * 32;
    for (int idx = blockIdx.x * blockDim.x + threadIdx.x; idx < total;
         idx += gridDim.x * blockDim.x) {
        const int k   = idx & 31;
        const int n   = (idx >> 5) & 127;
        const int blk = idx >> 12;                 // nt*8 + kc
        const int kc  = blk & 7, nt = blk >> 3;
        const float v = w[(size_t)(kc * 32 + k) * LDB + nt * 128 + n];
        dst[(size_t)(blk * 128 + n) * AST + k] = f2tf32(v);
    }
}

// ---------------------------------------------------------------------------
// tf32 mma.sync GEMM: C[128 x NT*128] = A[128x256] @ W + bias
// 8 warps: wm = wid&3 (32-row band), wn = wid>>2 (64-col band)
// ---------------------------------------------------------------------------
template <int NT, bool LINEAR_A, bool LINEAR_OUT, bool SHIFT>
__global__ __launch_bounds__(256, 1)
void gemm_mma(const float* __restrict__ A, const uint32_t* __restrict__ Bp,
              const float* __restrict__ bias, float* __restrict__ Out)
{
    constexpr int LDB = NT * 128;
    extern __shared__ char sm[];
    uint32_t* As = (uint32_t*)sm;                       // 8 x [128][36]
    uint32_t* Bs = (uint32_t*)(sm + 8 * CHUNK_B);       // 2 x [128][36]
    const uint32_t smb = smem_u32(sm);

    const int tid  = threadIdx.x;
    const int lane = tid & 31;
    const int wid  = tid >> 5;
    const int wm   = wid & 3;
    const int wn   = wid >> 2;
    const int mt   = blockIdx.x;

    // ---- A gather + tf32 convert into 8 K-chunk smem tiles ----
    {
        const int row = tid >> 1;
        const int T   = mt * 128 + row;
        const float* arow = LINEAR_A ? (A + (size_t)T * 256)
                                     : (A + tok_img_off<SHIFT>(T));
#pragma unroll
        for (int j = 0; j < 32; j++) {
            const int c4  = (tid & 1) * 32 + j;         // float4 index 0..63
            const float4 v = *((const float4*)arow + c4);
            const int col = c4 * 4;
            const int kc  = col >> 5, k = col & 31;
            uint4 u = { f2tf32(v.x), f2tf32(v.y), f2tf32(v.z), f2tf32(v.w) };
            *(uint4*)(As + (size_t)kc * (128 * AST) + row * AST + k) = u;
        }
    }

    // ldmatrix lane addressing
    const int a_row = (lane & 7) + ((lane >> 3) & 1) * 8;   // 0..15
    const int a_k   = ((lane >> 4) & 1) * 4;                // 0 or 4
    const int b_n   = (lane & 7);
    const int b_k   = (lane >> 3) * 4;                      // 0,4,8,12

    float acc[2][8][4];
    const int total_cc = NT * 8;

    // prologue: copy B chunk 0
    {
        const uint32_t* src = Bp + 0;
#pragma unroll
        for (int j = 0; j < 5; j++) {
            const int i = tid + j * 256;
            if (i < 1152) ((uint4*)Bs)[i] = ((const uint4*)src)[i];
        }
    }
    __syncthreads();

    for (int cc = 0; cc < total_cc; cc++) {
        const int nt  = cc >> 3;
        const int kc  = cc & 7;
        const int buf = cc & 1;

        if (kc == 0) {
#pragma unroll
            for (int mi = 0; mi < 2; mi++)
#pragma unroll
                for (int ni = 0; ni < 8; ni++)
#pragma unroll
                    for (int e = 0; e < 4; e++) acc[mi][ni][e] = 0.f;
        }

        // prefetch next B chunk into registers
        uint4 pf[5];
        const bool more = (cc + 1 < total_cc);
        if (more) {
            const uint4* src = (const uint4*)(Bp + (size_t)(cc + 1) * (128 * AST));
#pragma unroll
            for (int j = 0; j < 5; j++) {
                const int i = tid + j * 256;
                if (i < 1152) pf[j] = src[i];
            }
        }

        // ---- compute this chunk ----
        const uint32_t a_base = smb + kc * CHUNK_B
                              + ((wm * 32 + a_row) * AST) * 4;
        const uint32_t b_base = smb + 8 * CHUNK_B + buf * CHUNK_B
                              + ((wn * 64 + b_n) * AST) * 4;
#pragma unroll
        for (int kp = 0; kp < 2; kp++) {
            uint32_t bf[8][4];
#pragma unroll
            for (int ni = 0; ni < 8; ni++)
                ldsm_x4(bf[ni], b_base + (ni * 8) * AST * 4 + (kp * 16 + b_k) * 4);
#pragma unroll
            for (int half = 0; half < 2; half++) {
                const int ks = kp * 2 + half;
                uint32_t af[2][4];
#pragma unroll
                for (int mi = 0; mi < 2; mi++)
                    ldsm_x4(af[mi], a_base + (mi * 16) * AST * 4 + (ks * 8 + a_k) * 4);
#pragma unroll
                for (int mi = 0; mi < 2; mi++)
#pragma unroll
                    for (int ni = 0; ni < 8; ni++)
                        mma_tf32(acc[mi][ni], af[mi],
                                 bf[ni][half * 2], bf[ni][half * 2 + 1]);
            }
        }
        __syncthreads();
        if (more) {
            uint32_t* dstb = Bs + (size_t)((cc + 1) & 1) * (128 * AST);
#pragma unroll
            for (int j = 0; j < 5; j++) {
                const int i = tid + j * 256;
                if (i < 1152) ((uint4*)dstb)[i] = pf[j];
            }
            __syncthreads();
        }

        // ---- epilogue at the end of each n-tile ----
        if (kc == 7) {
            const int g  = lane >> 2, tg = lane & 3;
            const int nb = nt * 128 + wn * 64;
#pragma unroll
            for (int mi = 0; mi < 2; mi++) {
#pragma unroll
                for (int hr = 0; hr < 2; hr++) {
                    const int T = mt * 128 + wm * 32 + mi * 16 + g + hr * 8;
                    float* orow = LINEAR_OUT ? (Out + (size_t)T * LDB)
                                             : (Out + tok_img_off<SHIFT>(T));
#pragma unroll
                    for (int ni = 0; ni < 8; ni++) {
                        const int c = nb + ni * 8 + 2 * tg;
                        const float b0 = bias[c], b1 = bias[c + 1];
                        float2 v;
                        v.x = acc[mi][ni][hr * 2]     + b0;
                        v.y = acc[mi][ni][hr * 2 + 1] + b1;
                        *(float2*)(orow + c) = v;
                    }
                }
            }
        }
    }
}

// ---------------------------------------------------------------------------
// per-window attention (fp32): softmax(QK^T * scale [+mask]) @ V
// ---------------------------------------------------------------------------
template <bool MASKED>
__global__ __launch_bounds__(256, 4)
void attn_kernel(const float* __restrict__ qkv, float* __restrict__ ao)
{
    __shared__ float q [64][33];
    __shared__ float kT[32][65];
    __shared__ float v [64][33];
    __shared__ float sc[64][65];
    __shared__ int   regid[64];

    const int t    = threadIdx.x;
    const int lane = t & 31;
    const int wrp  = t >> 5;
    const int win  = blockIdx.x;
    const size_t Tb = (size_t)win * 64;

    if (MASKED && t < 64) {
        const int w = win & 63;
        const int gr = (w >> 3) * 8 + (t >> 3);
        const int gc = (w & 7) * 8 + (t & 7);
        const int rr = (gr < 56) ? 0 : (gr < 60 ? 1 : 2);
        const int cc = (gc < 56) ? 0 : (gc < 60 ? 1 : 2);
        regid[t] = rr * 3 + cc;
    }

    for (int h = 0; h < 8; h++) {
        for (int i = t; i < 2048; i += 256) {
            const int r = i >> 5, c = i & 31;
            const float* base = qkv + (Tb + r) * 768 + h * 32 + c;
            q[r][c]  = base[0];
            kT[c][r] = base[256];
            v[r][c]  = base[512];
        }
        __syncthreads();

#pragma unroll
        for (int ii = 0; ii < 8; ii++) {
            const int i = wrp + 8 * ii;
            float s0 = 0.f, s1 = 0.f;
#pragma unroll
            for (int d = 0; d < 32; d++) {
                const float qv = q[i][d];
                s0 = fmaf(qv, kT[d][lane],      s0);
                s1 = fmaf(qv, kT[d][lane + 32], s1);
            }
            s0 *= SCALE; s1 *= SCALE;
            if (MASKED) {
                const int ri = regid[i];
                if (ri != regid[lane])      s0 += NEGM;
                if (ri != regid[lane + 32]) s1 += NEGM;
            }
            sc[i][lane]      = s0;
            sc[i][lane + 32] = s1;
        }
        __syncthreads();

        {
            const int row = t >> 2, sub = t & 3;
            float* sr = &sc[row][sub * 16];
            float mx = sr[0];
#pragma unroll
            for (int k = 1; k < 16; k++) mx = fmaxf(mx, sr[k]);
            mx = fmaxf(mx, __shfl_xor_sync(0xffffffffu, mx, 1));
            mx = fmaxf(mx, __shfl_xor_sync(0xffffffffu, mx, 2));
            float sum = 0.f;
#pragma unroll
            for (int k = 0; k < 16; k++) {
                const float e = __expf(sr[k] - mx);
                sr[k] = e;
                sum += e;
            }
            sum += __shfl_xor_sync(0xffffffffu, sum, 1);
            sum += __shfl_xor_sync(0xffffffffu, sum, 2);
            const float inv = 1.0f / sum;
#pragma unroll
            for (int k = 0; k < 16; k++) sr[k] *= inv;
        }
        __syncthreads();

        {
            float acc[8];
#pragma unroll
            for (int ii = 0; ii < 8; ii++) acc[ii] = 0.f;
            for (int j = 0; j < 64; j++) {
                const float vv = v[j][lane];
#pragma unroll
                for (int ii = 0; ii < 8; ii++)
                    acc[ii] = fmaf(sc[wrp + 8 * ii][j], vv, acc[ii]);
            }
#pragma unroll
            for (int ii = 0; ii < 8; ii++)
                ao[(Tb + wrp + 8 * ii) * 256 + h * 32 + lane] = acc[ii];
        }
        __syncthreads();
    }
}

// ---------------------------------------------------------------------------
extern "C" void kernel_launch(void* const* d_in, const int* in_sizes, int n_in,
                              void* d_out, int out_size)
{
    const float* x    = (const float*)d_in[0];
    const float* wqkv = (const float*)d_in[1];
    const float* bqkv = (const float*)d_in[2];
    const float* wo   = (const float*)d_in[3];
    const float* bo   = (const float*)d_in[4];
    float* out = (float*)d_out;

    float *qkv_p, *ao_p, *y_p;
    uint32_t *wq_p, *wo_pk;
    cudaGetSymbolAddress((void**)&qkv_p, g_qkv);
    cudaGetSymbolAddress((void**)&ao_p,  g_ao);
    cudaGetSymbolAddress((void**)&y_p,   g_y);
    cudaGetSymbolAddress((void**)&wq_p,  g_wqkv_p);
    cudaGetSymbolAddress((void**)&wo_pk, g_wo_p);

    cudaFuncSetAttribute(gemm_mma<6, false, true,  false>,
                         cudaFuncAttributeMaxDynamicSharedMemorySize, GSMEM);
    cudaFuncSetAttribute(gemm_mma<6, false, true,  true>,
                         cudaFuncAttributeMaxDynamicSharedMemorySize, GSMEM);
    cudaFuncSetAttribute(gemm_mma<2, true,  false, false>,
                         cudaFuncAttributeMaxDynamicSharedMemorySize, GSMEM);
    cudaFuncSetAttribute(gemm_mma<2, true,  false, true>,
                         cudaFuncAttributeMaxDynamicSharedMemorySize, GSMEM);

    prepack_w<<<192, 256>>>(wqkv, wq_p, 6);
    prepack_w<<<64,  256>>>(wo,   wo_pk, 2);

    // pass 1 (unshifted)
    gemm_mma<6, false, true,  false><<<MT, 256, GSMEM>>>(x,    wq_p,  bqkv, qkv_p);
    attn_kernel<false><<<2048, 256>>>(qkv_p, ao_p);
    gemm_mma<2, true,  false, false><<<MT, 256, GSMEM>>>(ao_p, wo_pk, bo,   y_p);
    // pass 2 (shifted + mask)
    gemm_mma<6, false, true,  true ><<<MT, 256, GSMEM>>>(y_p,  wq_p,  bqkv, qkv_p);
    attn_kernel<true><<<2048, 256>>>(qkv_p, ao_p);
    gemm_mma<2, true,  false, true ><<<MT, 256, GSMEM>>>(ao_p, wo_pk, bo,   out);
}

// round 8
// speedup vs baseline: 4.8220x; 1.5934x over previous
#include <cuda_runtime.h>
#include <cstdint>

// ===========================================================================
// SWIN attention layer on GB300 (sm_103 base target — NO tcgen05).
// All GEMM-like work on tensor pipe via mma.sync.m16n8k8.tf32 + ldmatrix.
// Pipeline per pass: QKV GEMM -> per-window tensor-core attention -> proj GEMM
// ===========================================================================

namespace {
constexpr int TOK = 32 * 64 * 64;          // 131072 tokens
constexpr int MT  = TOK / 128;             // 1024 M-tiles
constexpr float SCALE = 0.17677669529663687f;
constexpr float NEGM  = -1e9f;
constexpr int AST = 36;                    // GEMM smem row stride (floats)
constexpr int CHUNK_B = 128 * AST * 4;     // 18432 B per [128][36] tile
constexpr int GSMEM = 8 * CHUNK_B + 2 * CHUNK_B;

// attention smem layout (floats), per CTA; per-head slices inside
constexpr int QS_OFF = 0;                          // [8][16][36]
constexpr int KS_OFF = QS_OFF + 8 * 16 * 36;       // [8][64][36]
constexpr int VT_OFF = KS_OFF + 8 * 64 * 36;       // [8][32][68]
constexpr int PB_OFF = VT_OFF + 8 * 32 * 68;       // [8][16][68]
constexpr int ASMEM  = (PB_OFF + 8 * 16 * 68) * 4; // 196608 B
}

// static device scratch
__device__ float    g_qkv[(size_t)TOK * 768];
__device__ float    g_ao [(size_t)TOK * 256];
__device__ float    g_y  [(size_t)TOK * 256];
__device__ uint32_t g_wqkv_p[6 * 8 * 128 * AST];
__device__ uint32_t g_wo_p  [2 * 8 * 128 * AST];

__device__ __forceinline__ uint32_t smem_u32(const void* p) {
    uint32_t a;
    asm("{ .reg .u64 t; cvta.to.shared.u64 t, %1; cvt.u32.u64 %0, t; }"
        : "=r"(a) : "l"(p));
    return a;
}
__device__ __forceinline__ uint32_t f2tf32(float f) {
    uint32_t u;
    asm("cvt.rna.tf32.f32 %0, %1;" : "=r"(u) : "f"(f));
    return u;
}
__device__ __forceinline__ float f2tf32f(float f) {
    return __uint_as_float(f2tf32(f));
}
__device__ __forceinline__ void ldsm_x4(uint32_t* r, uint32_t a) {
    asm volatile("ldmatrix.sync.aligned.m8n8.x4.shared.b16 {%0,%1,%2,%3}, [%4];"
                 : "=r"(r[0]), "=r"(r[1]), "=r"(r[2]), "=r"(r[3]) : "r"(a));
}
__device__ __forceinline__ void mma_tf32(float* c, const uint32_t* a,
                                         uint32_t b0, uint32_t b1) {
    asm volatile(
        "mma.sync.aligned.m16n8k8.row.col.f32.tf32.tf32.f32 "
        "{%0,%1,%2,%3}, {%4,%5,%6,%7}, {%8,%9}, {%0,%1,%2,%3};"
        : "+f"(c[0]), "+f"(c[1]), "+f"(c[2]), "+f"(c[3])
        : "r"(a[0]), "r"(a[1]), "r"(a[2]), "r"(a[3]), "r"(b0), "r"(b1));
}

template <bool SHIFT>
__device__ __forceinline__ size_t tok_img_off(int T) {
    const int win = T >> 6, pos = T & 63;
    const int b = win >> 6, w = win & 63;
    int gr = (w >> 3) * 8 + (pos >> 3);
    int gc = (w & 7) * 8 + (pos & 7);
    if (SHIFT) { gr = (gr + 4) & 63; gc = (gc + 4) & 63; }
    return ((size_t)((b * 64 + gr) * 64 + gc)) * 256;
}
__device__ __forceinline__ int regid_of(int w, int pos) {
    const int gr = (w >> 3) * 8 + (pos >> 3);
    const int gc = (w & 7) * 8 + (pos & 7);
    const int rr = (gr < 56) ? 0 : (gr < 60 ? 1 : 2);
    const int cc = (gc < 56) ? 0 : (gc < 60 ? 1 : 2);
    return rr * 3 + cc;
}

// ---------------------------------------------------------------------------
// weight pre-pack (validated)
// ---------------------------------------------------------------------------
__global__ void prepack_w(const float* __restrict__ w, uint32_t* __restrict__ dst,
                          int NT)
{
    const int LDB = NT * 128;
    const int total = NT * 8 * 128 * 32;
    for (int idx = blockIdx.x * blockDim.x + threadIdx.x; idx < total;
         idx += gridDim.x * blockDim.x) {
        const int k   = idx & 31;
        const int n   = (idx >> 5) & 127;
        const int blk = idx >> 12;
        const int kc  = blk & 7, nt = blk >> 3;
        const float v = w[(size_t)(kc * 32 + k) * LDB + nt * 128 + n];
        dst[(size_t)(blk * 128 + n) * AST + k] = f2tf32(v);
    }
}

// ---------------------------------------------------------------------------
// tf32 mma.sync GEMM (validated in R5)
// ---------------------------------------------------------------------------
template <int NT, bool LINEAR_A, bool LINEAR_OUT, bool SHIFT>
__global__ __launch_bounds__(256, 1)
void gemm_mma(const float* __restrict__ A, const uint32_t* __restrict__ Bp,
              const float* __restrict__ bias, float* __restrict__ Out)
{
    constexpr int LDB = NT * 128;
    extern __shared__ char smraw[];
    uint32_t* As = (uint32_t*)smraw;
    uint32_t* Bs = (uint32_t*)(smraw + 8 * CHUNK_B);
    const uint32_t smb = smem_u32(smraw);

    const int tid  = threadIdx.x;
    const int lane = tid & 31;
    const int wid  = tid >> 5;
    const int wm   = wid & 3;
    const int wn   = wid >> 2;
    const int mt   = blockIdx.x;

    {
        const int row = tid >> 1;
        const int T   = mt * 128 + row;
        const float* arow = LINEAR_A ? (A + (size_t)T * 256)
                                     : (A + tok_img_off<SHIFT>(T));
#pragma unroll
        for (int j = 0; j < 32; j++) {
            const int c4  = (tid & 1) * 32 + j;
            const float4 v = *((const float4*)arow + c4);
            const int col = c4 * 4;
            const int kc  = col >> 5, k = col & 31;
            uint4 u = { f2tf32(v.x), f2tf32(v.y), f2tf32(v.z), f2tf32(v.w) };
            *(uint4*)(As + (size_t)kc * (128 * AST) + row * AST + k) = u;
        }
    }

    const int a_row = (lane & 7) + ((lane >> 3) & 1) * 8;
    const int a_k   = ((lane >> 4) & 1) * 4;
    const int b_n   = (lane & 7);
    const int b_k   = (lane >> 3) * 4;

    float acc[2][8][4];
    const int total_cc = NT * 8;

    {
#pragma unroll
        for (int j = 0; j < 5; j++) {
            const int i = tid + j * 256;
            if (i < 1152) ((uint4*)Bs)[i] = ((const uint4*)Bp)[i];
        }
    }
    __syncthreads();

    for (int cc = 0; cc < total_cc; cc++) {
        const int nt  = cc >> 3;
        const int kc  = cc & 7;
        const int buf = cc & 1;

        if (kc == 0) {
#pragma unroll
            for (int mi = 0; mi < 2; mi++)
#pragma unroll
                for (int ni = 0; ni < 8; ni++)
#pragma unroll
                    for (int e = 0; e < 4; e++) acc[mi][ni][e] = 0.f;
        }

        uint4 pf[5];
        const bool more = (cc + 1 < total_cc);
        if (more) {
            const uint4* src = (const uint4*)(Bp + (size_t)(cc + 1) * (128 * AST));
#pragma unroll
            for (int j = 0; j < 5; j++) {
                const int i = tid + j * 256;
                if (i < 1152) pf[j] = src[i];
            }
        }

        const uint32_t a_base = smb + kc * CHUNK_B + ((wm * 32 + a_row) * AST) * 4;
        const uint32_t b_base = smb + 8 * CHUNK_B + buf * CHUNK_B
                              + ((wn * 64 + b_n) * AST) * 4;
#pragma unroll
        for (int kp = 0; kp < 2; kp++) {
            uint32_t bf[8][4];
#pragma unroll
            for (int ni = 0; ni < 8; ni++)
                ldsm_x4(bf[ni], b_base + (ni * 8) * AST * 4 + (kp * 16 + b_k) * 4);
#pragma unroll
            for (int half = 0; half < 2; half++) {
                const int ks = kp * 2 + half;
                uint32_t af[2][4];
#pragma unroll
                for (int mi = 0; mi < 2; mi++)
                    ldsm_x4(af[mi], a_base + (mi * 16) * AST * 4 + (ks * 8 + a_k) * 4);
#pragma unroll
                for (int mi = 0; mi < 2; mi++)
#pragma unroll
                    for (int ni = 0; ni < 8; ni++)
                        mma_tf32(acc[mi][ni], af[mi],
                                 bf[ni][half * 2], bf[ni][half * 2 + 1]);
            }
        }
        __syncthreads();
        if (more) {
            uint32_t* dstb = Bs + (size_t)((cc + 1) & 1) * (128 * AST);
#pragma unroll
            for (int j = 0; j < 5; j++) {
                const int i = tid + j * 256;
                if (i < 1152) ((uint4*)dstb)[i] = pf[j];
            }
            __syncthreads();
        }

        if (kc == 7) {
            const int g  = lane >> 2, tg = lane & 3;
            const int nb = nt * 128 + wn * 64;
#pragma unroll
            for (int mi = 0; mi < 2; mi++) {
#pragma unroll
                for (int hr = 0; hr < 2; hr++) {
                    const int T = mt * 128 + wm * 32 + mi * 16 + g + hr * 8;
                    float* orow = LINEAR_OUT ? (Out + (size_t)T * LDB)
                                             : (Out + tok_img_off<SHIFT>(T));
#pragma unroll
                    for (int ni = 0; ni < 8; ni++) {
                        const int c = nb + ni * 8 + 2 * tg;
                        float2 v;
                        v.x = acc[mi][ni][hr * 2]     + bias[c];
                        v.y = acc[mi][ni][hr * 2 + 1] + bias[c + 1];
                        *(float2*)(orow + c) = v;
                    }
                }
            }
        }
    }
}

// ---------------------------------------------------------------------------
// tensor-core attention: CTA = window, warp = head, warp-synchronous.
// S = QK^T (tf32 mma), reg softmax, P@V (tf32 mma).
// ---------------------------------------------------------------------------
template <bool MASKED>
__global__ __launch_bounds__(256, 1)
void attn_mma(const float* __restrict__ qkv, float* __restrict__ ao)
{
    extern __shared__ char smraw[];
    float* smf = (float*)smraw;
    const int t    = threadIdx.x;
    const int lane = t & 31;
    const int h    = t >> 5;           // warp = head
    const int win  = blockIdx.x;
    const int w    = win & 63;
    const size_t Tb = (size_t)win * 64;

    float* qs = smf + QS_OFF + h * (16 * 36);
    float* ks = smf + KS_OFF + h * (64 * 36);
    float* vt = smf + VT_OFF + h * (32 * 68);
    float* pb = smf + PB_OFF + h * (16 * 68);

    const float* hb = qkv + Tb * 768 + h * 32;

    // ---- stage K [64 tok][32 dim] and V^T [32 dim][64 tok], tf32 ----
#pragma unroll
    for (int it = 0; it < 16; it++) {
        const int tok = it * 4 + (lane >> 3);
        const int d4  = lane & 7;
        const float4 kv = *(const float4*)(hb + (size_t)tok * 768 + 256 + d4 * 4);
        uint4 u = { f2tf32(kv.x), f2tf32(kv.y), f2tf32(kv.z), f2tf32(kv.w) };
        *(uint4*)(ks + tok * 36 + d4 * 4) = u;
        const float4 vv = *(const float4*)(hb + (size_t)tok * 768 + 512 + d4 * 4);
        const int db = d4 * 4;
        vt[(db + 0) * 68 + tok] = f2tf32f(vv.x);
        vt[(db + 1) * 68 + tok] = f2tf32f(vv.y);
        vt[(db + 2) * 68 + tok] = f2tf32f(vv.z);
        vt[(db + 3) * 68 + tok] = f2tf32f(vv.w);
    }

    const int g  = lane >> 2, tg = lane & 3;
    const int a_row = (lane & 7) + ((lane >> 3) & 1) * 8;
    const int a_k   = ((lane >> 4) & 1) * 4;
    const int b_n   = lane & 7;
    const int b_k   = (lane >> 3) * 4;

    const uint32_t qs_lm = smem_u32(qs) + (a_row * 36) * 4;
    const uint32_t pb_lm = smem_u32(pb) + (a_row * 68) * 4;
    const uint32_t ks_lm = smem_u32(ks) + (b_n * 36) * 4;
    const uint32_t vt_lm = smem_u32(vt) + (b_n * 68) * 4;

    int rid_c[16];
    if (MASKED) {
#pragma unroll
        for (int ni = 0; ni < 8; ni++) {
            rid_c[ni * 2]     = regid_of(w, ni * 8 + 2 * tg);
            rid_c[ni * 2 + 1] = regid_of(w, ni * 8 + 2 * tg + 1);
        }
    }
    __syncwarp();

    for (int mi = 0; mi < 4; mi++) {
        // ---- Q block [16][32] ----
#pragma unroll
        for (int it = 0; it < 4; it++) {
            const int row = it * 4 + (lane >> 3);
            const int d4  = lane & 7;
            const float4 qv =
                *(const float4*)(hb + (size_t)(mi * 16 + row) * 768 + d4 * 4);
            uint4 u = { f2tf32(qv.x), f2tf32(qv.y), f2tf32(qv.z), f2tf32(qv.w) };
            *(uint4*)(qs + row * 36 + d4 * 4) = u;
        }
        __syncwarp();

        // ---- S = Q K^T : acc s[8 n-tiles][4] ----
        float s[8][4];
#pragma unroll
        for (int ni = 0; ni < 8; ni++)
#pragma unroll
            for (int e = 0; e < 4; e++) s[ni][e] = 0.f;
#pragma unroll
        for (int kp = 0; kp < 2; kp++) {
            uint32_t bf[8][4];
#pragma unroll
            for (int ni = 0; ni < 8; ni++)
                ldsm_x4(bf[ni], ks_lm + (ni * 8) * 36 * 4 + (kp * 16 + b_k) * 4);
#pragma unroll
            for (int half = 0; half < 2; half++) {
                const int ksx = kp * 2 + half;
                uint32_t af[4];
                ldsm_x4(af, qs_lm + (ksx * 8 + a_k) * 4);
#pragma unroll
                for (int ni = 0; ni < 8; ni++)
                    mma_tf32(s[ni], af, bf[ni][half * 2], bf[ni][half * 2 + 1]);
            }
        }

        // ---- scale + mask ----
        int r0 = 0, r1 = 0;
        if (MASKED) {
            r0 = regid_of(w, mi * 16 + g);
            r1 = regid_of(w, mi * 16 + g + 8);
        }
#pragma unroll
        for (int ni = 0; ni < 8; ni++) {
#pragma unroll
            for (int e = 0; e < 2; e++) {
                s[ni][e]     = s[ni][e] * SCALE
                             + ((MASKED && r0 != rid_c[ni * 2 + e]) ? NEGM : 0.f);
                s[ni][2 + e] = s[ni][2 + e] * SCALE
                             + ((MASKED && r1 != rid_c[ni * 2 + e]) ? NEGM : 0.f);
            }
        }

        // ---- softmax (rows g and g+8; 4 lanes per row) ----
        float m0 = -3.0e38f, m1 = -3.0e38f;
#pragma unroll
        for (int ni = 0; ni < 8; ni++) {
            m0 = fmaxf(m0, fmaxf(s[ni][0], s[ni][1]));
            m1 = fmaxf(m1, fmaxf(s[ni][2], s[ni][3]));
        }
        m0 = fmaxf(m0, __shfl_xor_sync(0xffffffffu, m0, 1));
        m0 = fmaxf(m0, __shfl_xor_sync(0xffffffffu, m0, 2));
        m1 = fmaxf(m1, __shfl_xor_sync(0xffffffffu, m1, 1));
        m1 = fmaxf(m1, __shfl_xor_sync(0xffffffffu, m1, 2));
        float sum0 = 0.f, sum1 = 0.f;
#pragma unroll
        for (int ni = 0; ni < 8; ni++) {
            s[ni][0] = __expf(s[ni][0] - m0); sum0 += s[ni][0];
            s[ni][1] = __expf(s[ni][1] - m0); sum0 += s[ni][1];
            s[ni][2] = __expf(s[ni][2] - m1); sum1 += s[ni][2];
            s[ni][3] = __expf(s[ni][3] - m1); sum1 += s[ni][3];
        }
        sum0 += __shfl_xor_sync(0xffffffffu, sum0, 1);
        sum0 += __shfl_xor_sync(0xffffffffu, sum0, 2);
        sum1 += __shfl_xor_sync(0xffffffffu, sum1, 1);
        sum1 += __shfl_xor_sync(0xffffffffu, sum1, 2);
        const float i0 = 1.0f / sum0, i1 = 1.0f / sum1;

        // ---- P (tf32) -> pbuf ----
#pragma unroll
        for (int ni = 0; ni < 8; ni++) {
            float2 p0 = { f2tf32f(s[ni][0] * i0), f2tf32f(s[ni][1] * i0) };
            float2 p1 = { f2tf32f(s[ni][2] * i1), f2tf32f(s[ni][3] * i1) };
            *(float2*)(pb + g * 68 + ni * 8 + 2 * tg)       = p0;
            *(float2*)(pb + (g + 8) * 68 + ni * 8 + 2 * tg) = p1;
        }
        __syncwarp();

        // ---- O = P @ V : o[4 n-tiles][4] ----
        float o[4][4];
#pragma unroll
        for (int ni = 0; ni < 4; ni++)
#pragma unroll
            for (int e = 0; e < 4; e++) o[ni][e] = 0.f;
#pragma unroll
        for (int kp = 0; kp < 4; kp++) {
            uint32_t bf2[4][4];
#pragma unroll
            for (int ni = 0; ni < 4; ni++)
                ldsm_x4(bf2[ni], vt_lm + (ni * 8) * 68 * 4 + (kp * 16 + b_k) * 4);
#pragma unroll
            for (int half = 0; half < 2; half++) {
                const int ksx = kp * 2 + half;
                uint32_t af[4];
                ldsm_x4(af, pb_lm + (ksx * 8 + a_k) * 4);
#pragma unroll
                for (int ni = 0; ni < 4; ni++)
                    mma_tf32(o[ni], af, bf2[ni][half * 2], bf2[ni][half * 2 + 1]);
            }
        }
        __syncwarp();   // pbuf reads done; reuse as O staging

        // ---- stage O, then coalesced 128B writes ----
#pragma unroll
        for (int ni = 0; ni < 4; ni++) {
            *(float2*)(pb + g * 68 + ni * 8 + 2 * tg)       = make_float2(o[ni][0], o[ni][1]);
            *(float2*)(pb + (g + 8) * 68 + ni * 8 + 2 * tg) = make_float2(o[ni][2], o[ni][3]);
        }
        __syncwarp();
#pragma unroll
        for (int it = 0; it < 4; it++) {
            const int row = it * 4 + (lane >> 3);
            const int c4  = lane & 7;      // 8 lanes x float4 = 32 floats/row
            const float4 vv = *(const float4*)(pb + row * 68 + c4 * 4);
            *(float4*)(ao + (Tb + mi * 16 + row) * 256 + h * 32 + c4 * 4) = vv;
        }
        __syncwarp();   // before next mi overwrites qs/pb
    }
}

// ---------------------------------------------------------------------------
extern "C" void kernel_launch(void* const* d_in, const int* in_sizes, int n_in,
                              void* d_out, int out_size)
{
    const float* x    = (const float*)d_in[0];
    const float* wqkv = (const float*)d_in[1];
    const float* bqkv = (const float*)d_in[2];
    const float* wo   = (const float*)d_in[3];
    const float* bo   = (const float*)d_in[4];
    float* out = (float*)d_out;

    float *qkv_p, *ao_p, *y_p;
    uint32_t *wq_p, *wo_pk;
    cudaGetSymbolAddress((void**)&qkv_p, g_qkv);
    cudaGetSymbolAddress((void**)&ao_p,  g_ao);
    cudaGetSymbolAddress((void**)&y_p,   g_y);
    cudaGetSymbolAddress((void**)&wq_p,  g_wqkv_p);
    cudaGetSymbolAddress((void**)&wo_pk, g_wo_p);

    cudaFuncSetAttribute(gemm_mma<6, false, true,  false>,
                         cudaFuncAttributeMaxDynamicSharedMemorySize, GSMEM);
    cudaFuncSetAttribute(gemm_mma<6, false, true,  true>,
                         cudaFuncAttributeMaxDynamicSharedMemorySize, GSMEM);
    cudaFuncSetAttribute(gemm_mma<2, true,  false, false>,
                         cudaFuncAttributeMaxDynamicSharedMemorySize, GSMEM);
    cudaFuncSetAttribute(gemm_mma<2, true,  false, true>,
                         cudaFuncAttributeMaxDynamicSharedMemorySize, GSMEM);
    cudaFuncSetAttribute(attn_mma<false>,
                         cudaFuncAttributeMaxDynamicSharedMemorySize, ASMEM);
    cudaFuncSetAttribute(attn_mma<true>,
                         cudaFuncAttributeMaxDynamicSharedMemorySize, ASMEM);

    prepack_w<<<192, 256>>>(wqkv, wq_p, 6);
    prepack_w<<<64,  256>>>(wo,   wo_pk, 2);

    // pass 1 (unshifted)
    gemm_mma<6, false, true,  false><<<MT, 256, GSMEM>>>(x,    wq_p,  bqkv, qkv_p);
    attn_mma<false><<<2048, 256, ASMEM>>>(qkv_p, ao_p);
    gemm_mma<2, true,  false, false><<<MT, 256, GSMEM>>>(ao_p, wo_pk, bo,   y_p);
    // pass 2 (shifted + mask)
    gemm_mma<6, false, true,  true ><<<MT, 256, GSMEM>>>(y_p,  wq_p,  bqkv, qkv_p);
    attn_mma<true><<<2048, 256, ASMEM>>>(qkv_p, ao_p);
    gemm_mma<2, true,  false, true ><<<MT, 256, GSMEM>>>(ao_p, wo_pk, bo,   out);
}